// round 1
// baseline (speedup 1.0000x reference)
#include <cuda_runtime.h>

// NLSearch: non-local patch search.
// vid0, vid1: (1, 3, 32, 256, 256) float32.
// Query grid: 64x64 (stride 4). Patch 7x7, shift window 8x8 (offsets -4..3), K=7.
// Output (concatenated float32):
//   [0 .. 86016)          dists_out (1,1,12288,7)
//   [86016 .. 344064)     inds_out  (1,1,12288,7,3)  (t, hh, ww) as floats

__device__ __forceinline__ int refl(int x) {
    x = x < 0 ? -x : x;
    return x > 255 ? 510 - x : x;
}

__global__ void __launch_bounds__(256, 4)
nls_kernel(const float* __restrict__ vid0,
           const float* __restrict__ vid1,
           float* __restrict__ out)
{
    __shared__ float v1s[32 * 14 * 14];  // region rows/cols qh-7..qh+6 (reflected)
    __shared__ float v0s[32 * 7 * 7];    // patch rows/cols qh-3..qh+3 (reflected)
    __shared__ float sdist[64];

    const int b = blockIdx.x;
    const int t = b >> 12;           // / 4096
    const int r = b & 4095;
    const int n = r >> 6;
    const int v = r & 63;
    const int qh = n << 2;
    const int qw = v << 2;

    const float* __restrict__ V0 = vid0 + (size_t)t * 32 * 65536;
    const float* __restrict__ V1 = vid1 + (size_t)t * 32 * 65536;

    const int tid  = threadIdx.x;
    const int lane = tid & 31;
    const int w    = tid >> 5;       // warp id = s0 index (s0 = w - 4)

    // ---- stage inputs into SMEM (reflect applied here) ----
    for (int idx = tid; idx < 32 * 196; idx += 256) {
        int c   = idx / 196;
        int rem = idx - c * 196;
        int rr  = rem / 14;
        int cc  = rem - rr * 14;
        int hg  = refl(qh - 7 + rr);
        int wg  = refl(qw - 7 + cc);
        v1s[idx] = V1[(c << 16) + (hg << 8) + wg];
    }
    for (int idx = tid; idx < 32 * 49; idx += 256) {
        int c   = idx / 49;
        int rem = idx - c * 49;
        int ii  = rem / 7;
        int jj  = rem - ii * 7;
        int hg  = refl(qh - 3 + ii);
        int wg  = refl(qw - 3 + jj);
        v0s[idx] = V0[(c << 16) + (hg << 8) + wg];
    }
    __syncthreads();

    // ---- compute: warp w handles shifts idx = w*8 + s1 (s1 = 0..7) ----
    // lane owns 7 (c,i) pairs; register sliding window over j gives
    // 56 FMA per (7 + 14) LDS.
    float acc[8];
#pragma unroll
    for (int s = 0; s < 8; s++) acc[s] = 0.f;

#pragma unroll
    for (int p = 0; p < 7; p++) {
        int pair = lane + (p << 5);       // 0..223 over (c,i): pair = c*7 + i
        int c = pair / 7;
        int i = pair - c * 7;
        const float* ar = &v0s[(c * 7 + i) * 7];
        const float* br = &v1s[(c * 14 + (w + i)) * 14];
        float a[7], bb[14];
#pragma unroll
        for (int j = 0; j < 7; j++)  a[j]  = ar[j];
#pragma unroll
        for (int j = 0; j < 14; j++) bb[j] = br[j];
#pragma unroll
        for (int s = 0; s < 8; s++)
#pragma unroll
            for (int j = 0; j < 7; j++)
                acc[s] = fmaf(a[j], bb[j + s], acc[s]);
    }

    // warp-reduce the 8 partial dists
#pragma unroll
    for (int s = 0; s < 8; s++) {
        float val = acc[s];
#pragma unroll
        for (int o = 16; o > 0; o >>= 1)
            val += __shfl_xor_sync(0xffffffffu, val, o);
        if (lane == 0) sdist[(w << 3) + s] = val;
    }
    __syncthreads();

    // ---- top-7 selection (warp 0): value desc, index asc tie-break ----
    if (w == 0) {
        float d0 = sdist[lane];
        float d1 = sdist[lane + 32];
        // self shift index 36 gets +1e30 for selection only
        float a0 = d0;
        float a1 = (lane == 4) ? d1 + 1e30f : d1;

        const int q = t * 4096 + n * 64 + v;
        float* dbase = out + (size_t)q * 7;
        float* ibase = out + 86016 + (size_t)q * 21;

#pragma unroll
        for (int k = 0; k < 7; k++) {
            // per-lane best of its two candidates (equal -> smaller index = lane)
            float bv = (a0 >= a1) ? a0 : a1;
            int   bi = (a0 >= a1) ? lane : lane + 32;
#pragma unroll
            for (int o = 16; o > 0; o >>= 1) {
                float ov = __shfl_xor_sync(0xffffffffu, bv, o);
                int   oi = __shfl_xor_sync(0xffffffffu, bi, o);
                if (ov > bv || (ov == bv && oi < bi)) { bv = ov; bi = oi; }
            }
            // all lanes hold the same winner bi; retire it
            if (bi == lane)      a0 = -3.4e38f;
            if (bi == lane + 32) a1 = -3.4e38f;
            if (lane == 0) {
                dbase[k] = sdist[bi];               // original dist (not adjusted)
                int s0 = bi >> 3;
                int s1 = bi & 7;
                int hh = refl(qh + s0 - 4);
                int ww = refl(qw + s1 - 4);
                ibase[k * 3 + 0] = (float)t;
                ibase[k * 3 + 1] = (float)hh;
                ibase[k * 3 + 2] = (float)ww;
            }
        }
    }
}

extern "C" void kernel_launch(void* const* d_in, const int* in_sizes, int n_in,
                              void* d_out, int out_size)
{
    const float* vid0 = (const float*)d_in[0];
    const float* vid1 = (const float*)d_in[1];
    float* out = (float*)d_out;
    nls_kernel<<<12288, 256>>>(vid0, vid1, out);
}

// round 2
// speedup vs baseline: 1.7148x; 1.7148x over previous
#include <cuda_runtime.h>

// NLSearch: vid0, vid1 (1,3,32,256,256) f32. Query grid 64x64 stride 4,
// patch 7x7, shift window 8x8 (offsets -4..3), K=7.
// Output float32: [0,86016) dists (1,1,12288,7); [86016,344064) inds (..,7,3).

#define V1_CSTR 197   // 14*14=196 padded to 197 (odd mod 32 -> conflict-free)
#define V0_CSTR 49    // 7*7 = 49 (17 mod 32, conflict-free)

__device__ __forceinline__ int refl(int x) {
    x = x < 0 ? -x : x;
    return x > 255 ? 510 - x : x;
}

__global__ void __launch_bounds__(256, 4)
nls_kernel(const float* __restrict__ vid0,
           const float* __restrict__ vid1,
           float* __restrict__ out)
{
    __shared__ float v1s[32 * V1_CSTR]; // [c][r*14+cc], rows qh-7..qh+6 reflected
    __shared__ float v0s[32 * V0_CSTR]; // [c][ii*7+jj], rows qh-3..qh+3 reflected
    __shared__ float sdist[64];

    const int b = blockIdx.x;
    const int t = b >> 12;
    const int r = b & 4095;
    const int n = r >> 6;
    const int v = r & 63;
    const int qh = n << 2;
    const int qw = v << 2;

    const int tid  = threadIdx.x;
    const int lane = tid & 31;
    const int w    = tid >> 5;       // warp id = s0 index (s0 = w - 4)

    // ---- stage: thread->(element) fixed once, loop channels ----
    if (tid < 196) {
        // v1 region: 14x14, rows/cols qh-7..qh+6 (reflected)
        int rr = tid / 14;
        int cc = tid - rr * 14;
        int hg = refl(qh - 7 + rr);
        int wg = refl(qw - 7 + cc);
        const float* src = vid1 + (size_t)t * 32 * 65536 + (hg << 8) + wg;
        float* dst = v1s + tid;
#pragma unroll 8
        for (int c = 0; c < 32; c++) {
            dst[c * V1_CSTR] = src[c << 16];
        }
    } else if (tid < 196 + 49) {
        // v0 patch: 7x7, rows/cols qh-3..qh+3 (reflected)
        int idx = tid - 196;
        int ii = idx / 7;
        int jj = idx - ii * 7;
        int hg = refl(qh - 3 + ii);
        int wg = refl(qw - 3 + jj);
        const float* src = vid0 + (size_t)t * 32 * 65536 + (hg << 8) + wg;
        float* dst = v0s + idx;
#pragma unroll 8
        for (int c = 0; c < 32; c++) {
            dst[c * V0_CSTR] = src[c << 16];
        }
    }
    __syncthreads();

    // ---- compute: warp w = shift row s0; lane = channel c; loop i = patch row.
    // acc[s1] += v0[c][i][j] * v1[c][w+i][j+s1], j=0..6, s1=0..7.
    const float* a_base = v0s + lane * V0_CSTR;          // channel = lane
    const float* b_base = v1s + lane * V1_CSTR + w * 14; // row w within channel

    float acc[8];
#pragma unroll
    for (int s = 0; s < 8; s++) acc[s] = 0.f;

#pragma unroll
    for (int i = 0; i < 7; i++) {
        float a[7], bb[14];
        const float* ar = a_base + i * 7;
        const float* br = b_base + i * 14;
#pragma unroll
        for (int j = 0; j < 7; j++)  a[j]  = ar[j];
#pragma unroll
        for (int j = 0; j < 14; j++) bb[j] = br[j];
#pragma unroll
        for (int s = 0; s < 8; s++)
#pragma unroll
            for (int j = 0; j < 7; j++)
                acc[s] = fmaf(a[j], bb[j + s], acc[s]);
    }

    // warp-reduce 8 partials (sum over channels)
#pragma unroll
    for (int s = 0; s < 8; s++) {
        float val = acc[s];
#pragma unroll
        for (int o = 16; o > 0; o >>= 1)
            val += __shfl_xor_sync(0xffffffffu, val, o);
        if (lane == 0) sdist[(w << 3) + s] = val;
    }
    __syncthreads();

    // ---- top-7 (warp 0): value desc, index asc tie-break ----
    if (w == 0) {
        float a0 = sdist[lane];
        float a1 = sdist[lane + 32];
        float d1 = a1;
        if (lane == 4) a1 += 1e30f;   // self shift idx 36 boosted for selection

        const int q = t * 4096 + n * 64 + v;
        float* dbase = out + (size_t)q * 7;
        float* ibase = out + 86016 + (size_t)q * 21;

#pragma unroll
        for (int k = 0; k < 7; k++) {
            float bv = (a0 >= a1) ? a0 : a1;
            int   bi = (a0 >= a1) ? lane : lane + 32;
#pragma unroll
            for (int o = 16; o > 0; o >>= 1) {
                float ov = __shfl_xor_sync(0xffffffffu, bv, o);
                int   oi = __shfl_xor_sync(0xffffffffu, bi, o);
                if (ov > bv || (ov == bv && oi < bi)) { bv = ov; bi = oi; }
            }
            if (bi == lane)      a0 = -3.4e38f;
            if (bi == lane + 32) a1 = -3.4e38f;
            if (lane == 0) {
                dbase[k] = sdist[bi];
                int s0 = bi >> 3;
                int s1 = bi & 7;
                ibase[k * 3 + 0] = (float)t;
                ibase[k * 3 + 1] = (float)refl(qh + s0 - 4);
                ibase[k * 3 + 2] = (float)refl(qw + s1 - 4);
            }
        }
        (void)d1;
    }
}

extern "C" void kernel_launch(void* const* d_in, const int* in_sizes, int n_in,
                              void* d_out, int out_size)
{
    const float* vid0 = (const float*)d_in[0];
    const float* vid1 = (const float*)d_in[1];
    float* out = (float*)d_out;
    nls_kernel<<<12288, 256>>>(vid0, vid1, out);
}